// round 3
// baseline (speedup 1.0000x reference)
#include <cuda_runtime.h>
#include <math_constants.h>

// Problem constants
#define Bb   16
#define Dd   64
#define Hh   64
#define Ww   64
#define Kk   1024
#define HW   4096          // H*W
#define NPTS 65536         // B*H*W
#define QELEMS 4194304     // B*D*H*W = 16*64*64*64

// Tiling
#define KC   128           // codebook chunk held in smem
#define NCHUNK (Kk / KC)   // 8
#define TPB  128           // threads per block
#define PPB  256           // points per block (2 per thread)
#define NBLK (NPTS / PPB)  // 256

__device__ float g_enorm[Kk];
__device__ float g_partial[NBLK];

// ||e_k||^2 per code. e is [D,K] row-major.
__global__ void enorm_kernel(const float* __restrict__ e) {
    int k = blockIdx.x * blockDim.x + threadIdx.x;
    if (k < Kk) {
        float s = 0.f;
        #pragma unroll
        for (int d = 0; d < Dd; d++) {
            float v = e[d * Kk + k];
            s = fmaf(v, v, s);
        }
        g_enorm[k] = s;
    }
}

__global__ __launch_bounds__(TPB)
void vq_kernel(const float* __restrict__ x,
               const float* __restrict__ e,
               float* __restrict__ out,
               long long out_size) {
    __shared__ float es[KC * 65];   // [k][d] padded to 65 floats: conflict-free fill
    __shared__ float esn[KC];
    __shared__ float red[TPB];

    const int t  = threadIdx.x;
    const int p0 = blockIdx.x * PPB + t;        // point 0
    const int p1 = p0 + TPB;                    // point 1

    const int b0 = p0 >> 12, hw0 = p0 & 4095;   // p = b*4096 + h*64 + w
    const int b1 = p1 >> 12, hw1 = p1 & 4095;

    const size_t base0 = (size_t)b0 * ((size_t)Dd * HW) + hw0;
    const size_t base1 = (size_t)b1 * ((size_t)Dd * HW) + hw1;

    // Load both feature vectors into registers (coalesced across threads per d)
    float xa[Dd], xb[Dd];
    #pragma unroll
    for (int j = 0; j < Dd; j++) {
        xa[j] = x[base0 + (size_t)j * HW];
        xb[j] = x[base1 + (size_t)j * HW];
    }

    float bda = CUDART_INF_F, bdb = CUDART_INF_F;
    int   bka = 0, bkb = 0;

    for (int c = 0; c < NCHUNK; c++) {
        __syncthreads();
        // Stage codebook chunk: read coalesced along k, write padded [k][d]
        const int kbase = c * KC;
        #pragma unroll
        for (int d = 0; d < Dd; d++) {
            es[t * 65 + d] = e[d * Kk + kbase + t];
        }
        esn[t] = g_enorm[kbase + t];
        __syncthreads();

        #pragma unroll 1
        for (int k = 0; k < KC; k++) {
            const float* ek = &es[k * 65];
            float a0 = 0.f, a1 = 0.f, a2 = 0.f, a3 = 0.f;
            float c0 = 0.f, c1 = 0.f, c2 = 0.f, c3 = 0.f;
            #pragma unroll
            for (int j = 0; j < Dd; j += 4) {
                float e0 = ek[j], e1 = ek[j + 1], e2 = ek[j + 2], e3 = ek[j + 3];
                a0 = fmaf(xa[j],     e0, a0);
                a1 = fmaf(xa[j + 1], e1, a1);
                a2 = fmaf(xa[j + 2], e2, a2);
                a3 = fmaf(xa[j + 3], e3, a3);
                c0 = fmaf(xb[j],     e0, c0);
                c1 = fmaf(xb[j + 1], e1, c1);
                c2 = fmaf(xb[j + 2], e2, c2);
                c3 = fmaf(xb[j + 3], e3, c3);
            }
            float da = fmaf(-2.f, (a0 + a1) + (a2 + a3), esn[k]);
            float db = fmaf(-2.f, (c0 + c1) + (c2 + c3), esn[k]);
            int kg = kbase + k;
            if (da < bda) { bda = da; bka = kg; }   // strict <: first-min like argmin
            if (db < bdb) { bdb = db; bkb = kg; }
        }
    }

    // Epilogue: gather chosen codes, STE output, local squared-error sum
    float lsum = 0.f;
    #pragma unroll
    for (int d = 0; d < Dd; d++) {
        float qa = e[d * Kk + bka];
        float qb = e[d * Kk + bkb];
        float va = xa[d] + (qa - xa[d]);   // match jax straight-through arithmetic
        float vb = xb[d] + (qb - xb[d]);
        long long oa = (long long)(base0 + (size_t)d * HW);
        long long ob = (long long)(base1 + (size_t)d * HW);
        if (oa < out_size) out[oa] = va;
        if (ob < out_size) out[ob] = vb;
        float ea = xa[d] - qa;
        float eb = xb[d] - qb;
        lsum = fmaf(ea, ea, lsum);
        lsum = fmaf(eb, eb, lsum);
    }

    // encoding indices as float at [QELEMS + 2 + p]
    long long idxoff = (long long)QELEMS + 2;
    if (idxoff + p0 < out_size) out[idxoff + p0] = (float)bka;
    if (idxoff + p1 < out_size) out[idxoff + p1] = (float)bkb;

    // Deterministic block reduction of squared-error sum
    red[t] = lsum;
    __syncthreads();
    #pragma unroll
    for (int s = TPB / 2; s > 0; s >>= 1) {
        if (t < s) red[t] += red[t + s];
        __syncthreads();
    }
    if (t == 0) g_partial[blockIdx.x] = red[0];
}

// Single-thread deterministic final sum -> both losses (forward-identical)
__global__ void loss_kernel(float* __restrict__ out, long long out_size) {
    if (blockIdx.x == 0 && threadIdx.x == 0) {
        double s = 0.0;
        for (int i = 0; i < NBLK; i++) s += (double)g_partial[i];
        float mean = (float)(s / (double)QELEMS);
        long long off = (long long)QELEMS;
        if (off     < out_size) out[off]     = mean;  // dictionary_loss
        if (off + 1 < out_size) out[off + 1] = mean;  // commitment_loss
    }
}

extern "C" void kernel_launch(void* const* d_in, const int* in_sizes, int n_in,
                              void* d_out, int out_size) {
    const float* x = (const float*)d_in[0];
    const float* e = (const float*)d_in[1];
    // Defensive input-order check: x has 4,194,304 elems; e has 65,536
    if (n_in >= 2 && in_sizes[0] == Dd * Kk && in_sizes[1] == QELEMS) {
        const float* tmp = x; x = e; e = tmp;
    }
    float* out = (float*)d_out;
    long long osz = (long long)out_size;

    enorm_kernel<<<(Kk + 127) / 128, 128>>>(e);
    vq_kernel<<<NBLK, TPB>>>(x, e, out, osz);
    loss_kernel<<<1, 32>>>(out, osz);
}